// round 15
// baseline (speedup 1.0000x reference)
#include <cuda_runtime.h>

// diff_pred: 16-tap LPC FIR with mu-law decode/encode.
//   sig: (2048, 2400, 1) fp32   lpc: (2048, 15, 16) fp32   out: (2048, 2400, 1) fp32
//
// Persistent blocks + atomic tile stealing + cross-tile prefetch.
// Tile = 256 threads x 8 outputs = 2048 consecutive samples of the flattened
// (batch, t) index space; 2400 tiles total. Per tile: decode own 8 samples
// (prefetched last iteration), publish to double-buffered smem, one barrier,
// halo via uniform LDS (lanes 0/1 pre-stage the block-left halo), 16-tap
// register FIR in two 8-tap passes, mu-law encode, vector store.

#define NTAPS   16
#define T_LEN   2400
#define NFRAMES 15
#define OPT     8
#define SEGS    300               // T_LEN / OPT
#define SLOT    12                // smem floats per slot (conflict-free stride)
#define NTILES  2400              // (2048*300)/256
#define GRID    608

__device__ int g_ctr;             // tile counter, memsetAsync(0) each launch

__device__ __forceinline__ float ex2_fast(float a) {
    float r;
    asm("ex2.approx.ftz.f32 %0, %1;" : "=f"(r) : "f"(a));
    return r;
}

// mu-law decode: u2l(raw) = copysign(SINV*(2^(|raw-128|/16) - 1), raw-128)
__device__ __forceinline__ float u2l_fast(float raw) {
    const float SINV = 32768.0f / 255.0f;
    float t = fmaf(raw, 0.0625f, -8.0f);   // sign & 16x-scaled |raw-128|
    float e = ex2_fast(fabsf(t));
    float m = fmaf(SINV, e, -SINV);
    return copysignf(m, t);
}

__global__ __launch_bounds__(256, 4)
void diff_pred_79336635892364_kernel(const float* __restrict__ sig,
                                     const float* __restrict__ lpc,
                                     float* __restrict__ out)
{
    // slots 0,1 = staged block-left halo; slot tid+2 = thread tid's decoded samples
    __shared__ float xs[2][(256 + 2) * SLOT];
    __shared__ int   nxt_s[2];
    __shared__ int   first_s;

    const float SC = 255.0f / 32768.0f;
    const int tid = threadIdx.x;

    // ---- first tile via steal ----
    if (tid == 0) first_s = atomicAdd(&g_ctr, 1);
    __syncthreads();
    int t_cur = first_s;
    if (t_cur >= NTILES) return;          // uniform per block

    // ---- prefetch raw samples for first tile ----
    float raw[OPT];
    {
        int g  = t_cur * 256 + tid;
        int b  = g / SEGS;
        int s  = g - b * SEGS;
        const float4* sp = reinterpret_cast<const float4*>(
            sig + (size_t)b * T_LEN + s * OPT);
        reinterpret_cast<float4*>(raw)[0] = sp[0];
        reinterpret_cast<float4*>(raw)[1] = sp[1];
    }

    int p = 0;
    while (true) {
        const int g     = t_cur * 256 + tid;
        const int batch = g / SEGS;
        const int seg   = g - batch * SEGS;
        const int t0    = seg * OPT;

        // ---- steal next tile (latency hidden behind decode phase) ----
        if (tid == 0) nxt_s[p] = atomicAdd(&g_ctr, 1);

        // ---- prefetch lpc first half (consumed at FIR start) ----
        const float* __restrict__ crow =
            lpc + ((size_t)batch * NFRAMES + seg / 20) * NTAPS;   // 160/OPT = 20
        float c[8];
        reinterpret_cast<float4*>(c)[0] = reinterpret_cast<const float4*>(crow)[0];
        reinterpret_cast<float4*>(c)[1] = reinterpret_cast<const float4*>(crow)[1];

        // ---- decode own 8 samples, publish to smem slot tid+2 ----
        float x[NTAPS + OPT];
        #pragma unroll
        for (int k = 0; k < OPT; k++) x[NTAPS + k] = u2l_fast(raw[k]);
        {
            float4* sl = reinterpret_cast<float4*>(&xs[p][(tid + 2) * SLOT]);
            sl[0] = reinterpret_cast<const float4*>(&x[NTAPS])[0];
            sl[1] = reinterpret_cast<const float4*>(&x[NTAPS])[1];
        }

        // ---- lanes 0/1: stage block-left halo into slots 0/1 ----
        if (tid < 2) {
            int G0  = t_cur * 256;                // g of tid 0
            int b0  = G0 / SEGS;
            int s0  = G0 - b0 * SEGS;
            int t00 = s0 * OPT;
            const float* sr0 = sig + (size_t)b0 * T_LEN;
            // tid0 -> slot0 = samples [t00-16, t00-8) (needs s0>=2)
            // tid1 -> slot1 = samples [t00-8,  t00)   (needs s0>=1)
            int need = (tid == 0) ? 2 : 1;
            if (s0 >= need) {
                float hr[8], hd[8];
                const float4* hp = reinterpret_cast<const float4*>(
                    sr0 + t00 - 16 + tid * 8);
                reinterpret_cast<float4*>(hr)[0] = hp[0];
                reinterpret_cast<float4*>(hr)[1] = hp[1];
                #pragma unroll
                for (int k = 0; k < 8; k++) hd[k] = u2l_fast(hr[k]);
                float4* sl = reinterpret_cast<float4*>(&xs[p][tid * SLOT]);
                sl[0] = reinterpret_cast<const float4*>(hd)[0];
                sl[1] = reinterpret_cast<const float4*>(hd)[1];
            }
        }
        __syncthreads();

        const int t_next = nxt_s[p];

        // ---- prefetch next tile's raw samples (overlaps FIR/encode/store) ----
        if (t_next < NTILES) {
            int gn = t_next * 256 + tid;
            int bn = gn / SEGS;
            int sn = gn - bn * SEGS;
            const float4* sp = reinterpret_cast<const float4*>(
                sig + (size_t)bn * T_LEN + sn * OPT);
            reinterpret_cast<float4*>(raw)[0] = sp[0];
            reinterpret_cast<float4*>(raw)[1] = sp[1];
        }

        // ---- halo: uniform LDS from slots tid+1 (seg-1) and tid (seg-2) ----
        if (seg == 0) {
            #pragma unroll
            for (int k = 0; k < NTAPS; k++) x[k] = 0.0f;   // u2l(128) == 0
        } else {
            const float4* h1 = reinterpret_cast<const float4*>(&xs[p][(tid + 1) * SLOT]);
            reinterpret_cast<float4*>(&x[8])[0] = h1[0];
            reinterpret_cast<float4*>(&x[8])[1] = h1[1];
            if (seg == 1) {
                #pragma unroll
                for (int k = 0; k < 8; k++) x[k] = 0.0f;
            } else {
                const float4* h0 = reinterpret_cast<const float4*>(&xs[p][tid * SLOT]);
                reinterpret_cast<float4*>(&x[0])[0] = h0[0];
                reinterpret_cast<float4*>(&x[0])[1] = h0[1];
            }
        }

        // ---- 16-tap FIR over 8 outputs, two 8-tap passes ----
        float acc[OPT];
        #pragma unroll
        for (int i = 0; i < OPT; i++) acc[i] = c[0] * x[NTAPS + i];
        #pragma unroll
        for (int j = 1; j < 8; j++) {
            #pragma unroll
            for (int i = 0; i < OPT; i++)
                acc[i] = fmaf(c[j], x[NTAPS + i - j], acc[i]);
        }
        reinterpret_cast<float4*>(c)[0] = reinterpret_cast<const float4*>(crow + 8)[0];
        reinterpret_cast<float4*>(c)[1] = reinterpret_cast<const float4*>(crow + 8)[1];
        #pragma unroll
        for (int j = 8; j < NTAPS; j++) {
            #pragma unroll
            for (int i = 0; i < OPT; i++)
                acc[i] = fmaf(c[j - 8], x[NTAPS + i - j], acc[i]);
        }

        // ---- mu-law encode: clip(fma(copysign(16,-a), log2(1+SC*|a|), 128), 0, 255)
        #pragma unroll
        for (int i = 0; i < OPT; i++) {
            float a = acc[i];
            float v = __log2f(fmaf(SC, fabsf(a), 1.0f));   // >= 0
            float r = fmaf(copysignf(16.0f, -a), v, 128.0f);
            acc[i]  = fminf(fmaxf(r, 0.0f), 255.0f);
        }

        // ---- vector store ----
        float4* ov = reinterpret_cast<float4*>(out + (size_t)batch * T_LEN + t0);
        ov[0] = reinterpret_cast<const float4*>(acc)[0];
        ov[1] = reinterpret_cast<const float4*>(acc)[1];

        p ^= 1;
        if (t_next >= NTILES) break;
        t_cur = t_next;
    }
}

extern "C" void kernel_launch(void* const* d_in, const int* in_sizes, int n_in,
                              void* d_out, int out_size)
{
    const float* sig = (const float*)d_in[0];
    const float* lpc = (const float*)d_in[1];
    float* out = (float*)d_out;

    // reset tile counter (graph-capturable async memset on the same stream)
    void* ctr_ptr = nullptr;
    cudaGetSymbolAddress(&ctr_ptr, g_ctr);
    cudaMemsetAsync(ctr_ptr, 0, sizeof(int));

    diff_pred_79336635892364_kernel<<<GRID, 256>>>(sig, lpc, out);
}